// round 2
// baseline (speedup 1.0000x reference)
#include <cuda_runtime.h>
#include <cuda_bf16.h>
#include <cub/cub.cuh>

// ---------------- problem constants ----------------
#define BB 4
#define AA 10
#define LL 4096
#define NPROP (LL * AA)          // 40960 per batch
#define TOTAL (BB * NPROP)       // 163840
#define PRE_NMS 6000
#define POST_NMS 300
#define MWORDS 188               // ceil(6000/32)
#define NMS_THRESH_F 0.7f
#define MIN_SIZE_F 8.0f
#define FEAT_STRIDE 8
#define CLIP_MAX 32767.0f        // L*FEAT_STRIDE - 1

// ---------------- static device scratch (no allocations allowed) ----------------
__device__ float g_x1[TOTAL];
__device__ float g_x2[TOTAL];
__device__ float g_keys_in[TOTAL];
__device__ float g_keys_out[TOTAL];
__device__ int   g_vals_in[TOTAL];
__device__ int   g_vals_out[TOTAL];
__device__ int   g_seg_off[BB + 1] = {0, NPROP, 2 * NPROP, 3 * NPROP, 4 * NPROP};
__device__ unsigned char g_cub_temp[8 << 20];
__device__ float2 g_obox[BB * PRE_NMS];                 // sorted-order candidate boxes
__device__ unsigned g_mask[(size_t)BB * PRE_NMS * MWORDS]; // ~18 MB suppression bitmasks

__constant__ float c_scales[AA] = {2.f, 4.f, 5.f, 6.f, 8.f, 9.f, 10.f, 12.f, 14.f, 16.f};

// ---------------- kernel 1: decode proposals + scores ----------------
__global__ void compute_props(const float* __restrict__ scores_in,
                              const float* __restrict__ deltas_in) {
    int idx = blockIdx.x * blockDim.x + threadIdx.x;
    if (idx >= TOTAL) return;
    int b = idx / NPROP;
    int r = idx - b * NPROP;   // r = l*A + a
    int l = r / AA;
    int a = r - l * AA;

    const int base = b * (2 * AA) * LL;
    float score = scores_in[base + (AA + a) * LL + l];
    float d0    = deltas_in[base + (2 * a) * LL + l];
    float d1    = deltas_in[base + (2 * a + 1) * LL + l];

    float ws   = c_scales[a] * (float)FEAT_STRIDE;
    float ctrA = ((float)FEAT_STRIDE - 1.0f) * 0.5f;      // 3.5
    float shift = (float)(l * FEAT_STRIDE);
    float x1a = ctrA - 0.5f * (ws - 1.0f) + shift;
    float x2a = ctrA + 0.5f * (ws - 1.0f) + shift;

    float width = x2a - x1a + 1.0f;
    float ctr   = x1a + 0.5f * width;

    float pred_ctr = d0 * width + ctr;
    float pred_l   = expf(d1) * width;

    float x1 = pred_ctr - 0.5f * pred_l;
    float x2 = pred_ctr + 0.5f * pred_l;
    x1 = fminf(fmaxf(x1, 0.0f), CLIP_MAX);
    x2 = fminf(fmaxf(x2, 0.0f), CLIP_MAX);

    float ls = x2 - x1 + 1.0f;
    if (ls < MIN_SIZE_F) score = 0.0f;

    g_x1[idx] = x1;
    g_x2[idx] = x2;
    g_keys_in[idx] = score;
    g_vals_in[idx] = r;   // within-batch proposal index
}

// ---------------- kernel 2b: gather top-PRE_NMS boxes in sorted order ----------------
__global__ void gather_kernel() {
    int t = blockIdx.x * blockDim.x + threadIdx.x;
    if (t >= BB * PRE_NMS) return;
    int b = t / PRE_NMS;
    int i = t - b * PRE_NMS;
    int gi = b * NPROP + g_vals_out[b * NPROP + i];
    g_obox[t] = make_float2(g_x1[gi], g_x2[gi]);
}

// ---------------- kernel 3: pairwise suppression bitmask ----------------
// grid = (188 row-tiles, BB), 256 threads. Row i's word w has bit k set iff
// j = w*32+k satisfies j > i, j < PRE_NMS, and iou(i,j) > 0.7.
__global__ void mask_kernel() {
    __shared__ float2 jb[PRE_NMS];   // 48000 B static
    const int b  = blockIdx.y;
    const int i0 = blockIdx.x * 32;

    const float2* obox = g_obox + b * PRE_NMS;
    for (int j = threadIdx.x; j < PRE_NMS; j += blockDim.x) jb[j] = obox[j];
    __syncthreads();

    unsigned* mrow = g_mask + (size_t)b * PRE_NMS * MWORDS;
    for (int t = threadIdx.x; t < 32 * MWORDS; t += blockDim.x) {
        int r = t / MWORDS;
        int w = t - r * MWORDS;
        int i = i0 + r;
        int jbase = w * 32;
        unsigned word = 0u;
        if (jbase + 31 > i) {            // word contains some j > i
            float2 bi = jb[i];
            float leni = bi.y - bi.x + 1.0f;
            int kmin = i - jbase + 1; if (kmin < 0) kmin = 0;
            int kmax = PRE_NMS - jbase;  if (kmax > 32) kmax = 32;
            for (int k = kmin; k < kmax; ++k) {
                float2 bj = jb[jbase + k];
                float inter = fminf(bi.y, bj.y) - fmaxf(bi.x, bj.x) + 1.0f;
                if (inter > 0.0f) {      // iou==0 otherwise -> never > 0.7
                    float lenj = bj.y - bj.x + 1.0f;
                    float uni = leni + lenj - inter;
                    if (inter / uni > NMS_THRESH_F) word |= (1u << k);
                }
            }
        }
        mrow[(size_t)i * MWORDS + w] = word;
    }
}

// ---------------- kernel 4: serial greedy resolve (1 warp per batch) ----------------
__global__ void resolve_kernel(float* __restrict__ out) {
    __shared__ unsigned s_remv[MWORDS];
    const int b = blockIdx.x;
    const int lane = threadIdx.x;      // 32 threads

    for (int w = lane; w < MWORDS; w += 32) s_remv[w] = 0u;
    for (int i = lane; i < POST_NMS; i += 32) {
        float* o = out + (b * POST_NMS + i) * 3;
        o[0] = (float)b; o[1] = 0.0f; o[2] = 0.0f;
    }
    __syncwarp();

    const unsigned* mask = g_mask + (size_t)b * PRE_NMS * MWORDS;
    const float2* obox = g_obox + b * PRE_NMS;

    int kept = 0;
    for (int w = 0; w < MWORDS && kept < POST_NMS; ++w) {
        unsigned valid = (w == MWORDS - 1) ? 0xFFFFu : 0xFFFFFFFFu;
        unsigned alive = (~s_remv[w]) & valid;
        while (alive && kept < POST_NMS) {
            int k = __ffs(alive) - 1;
            int i = w * 32 + k;        // first alive bit is always kept
            if (lane == 0) {
                float2 bx = obox[i];
                float* o = out + (b * POST_NMS + kept) * 3;
                o[1] = bx.x; o[2] = bx.y;
            }
            kept++;
            const unsigned* row = mask + (size_t)i * MWORDS;
            for (int ww = w + lane; ww < MWORDS; ww += 32) {
                unsigned m = row[ww];
                if (m) s_remv[ww] |= m;   // each word owned by one lane
            }
            __syncwarp();
            alive = (~s_remv[w]) & valid & ~((2u << k) - 1u);
        }
    }
}

// ---------------- host launcher ----------------
extern "C" void kernel_launch(void* const* d_in, const int* in_sizes, int n_in,
                              void* d_out, int out_size) {
    (void)in_sizes; (void)n_in; (void)out_size;
    const float* scores = (const float*)d_in[0];
    const float* deltas = (const float*)d_in[1];
    float* out = (float*)d_out;

    float *kin, *kout; int *vin, *vout, *off; void* tmp;
    cudaGetSymbolAddress((void**)&kin,  g_keys_in);
    cudaGetSymbolAddress((void**)&kout, g_keys_out);
    cudaGetSymbolAddress((void**)&vin,  g_vals_in);
    cudaGetSymbolAddress((void**)&vout, g_vals_out);
    cudaGetSymbolAddress((void**)&off,  g_seg_off);
    cudaGetSymbolAddress((void**)&tmp,  g_cub_temp);

    compute_props<<<(TOTAL + 255) / 256, 256>>>(scores, deltas);

    size_t temp_bytes = sizeof(g_cub_temp);
    cub::DeviceSegmentedRadixSort::SortPairsDescending(
        tmp, temp_bytes,
        kin, kout, vin, vout,
        TOTAL, BB, off, off + 1,
        0, 32, (cudaStream_t)0);

    gather_kernel<<<(BB * PRE_NMS + 255) / 256, 256>>>();
    mask_kernel<<<dim3(MWORDS, BB), 256>>>();
    resolve_kernel<<<BB, 32>>>(out);
}